// round 6
// baseline (speedup 1.0000x reference)
#include <cuda_runtime.h>
#include <cuda_bf16.h>
#include <cstdint>

#define BATCH   4096
#define DIM     16
#define NRULES  1024
#define NCLS    10
#define IEXT    17
#define NCOLS   170
#define NPAD    192
#define KSPLIT  4
#define KTOT    3072                 // 3 passes x 1024 (ah*bh, ah*bl, al*bh)
#define KLOC    (KTOT / KSPLIT)      // 768
#define NCH     (KLOC / 64)          // 12

// single TU-wide dynamic smem symbol
extern __shared__ char dyn_smem[];

// ---------------- static device scratch ----------------
__device__ __nv_bfloat16 g_Zb[BATCH * 192];      // [b][zh(64)|zl(64)|zl2(64)]
__device__ __nv_bfloat16 g_OTb[NRULES * 192];    // one-hot bf16, [r][j] x3 copies
__device__ __nv_bfloat16 g_Ah[BATCH * NRULES];
__device__ __nv_bfloat16 g_Al[BATCH * NRULES];
__device__ __nv_bfloat16 g_Bh[NPAD * NRULES];
__device__ __nv_bfloat16 g_Bl[NPAD * NRULES];
__device__ float         g_Tp[KSPLIT * BATCH * NPAD];   // 12.6 MB partials

// ---------------- helpers ----------------
__device__ __forceinline__ uint32_t smem_u32(const void* p) {
    uint32_t a;
    asm("{ .reg .u64 t; cvta.to.shared.u64 t, %1; cvt.u32.u64 %0, t; }" : "=r"(a) : "l"(p));
    return a;
}
#define SWZ128(o) ((o) ^ (((o) >> 3) & 0x70))

#define CP_ASYNC16(dst, src) \
    asm volatile("cp.async.cg.shared.global [%0], [%1], 16;" :: "r"(dst), "l"(src))
#define CP_COMMIT() asm volatile("cp.async.commit_group;" ::: "memory")
#define CP_WAIT1()  asm volatile("cp.async.wait_group 1;" ::: "memory")
#define CP_WAIT0()  asm volatile("cp.async.wait_group 0;" ::: "memory")

#define LDSM_X4(r0, r1, r2, r3, addr)                                        \
    asm volatile("ldmatrix.sync.aligned.m8n8.x4.shared.b16 {%0,%1,%2,%3}, [%4];" \
        : "=r"(r0), "=r"(r1), "=r"(r2), "=r"(r3) : "r"(addr))

__device__ __forceinline__ void mma16816(float* c, const uint32_t* a, const uint32_t* b) {
    asm volatile(
        "mma.sync.aligned.m16n8k16.row.col.f32.bf16.bf16.f32 "
        "{%0,%1,%2,%3}, {%4,%5,%6,%7}, {%8,%9}, {%0,%1,%2,%3};"
        : "+f"(c[0]), "+f"(c[1]), "+f"(c[2]), "+f"(c[3])
        : "r"(a[0]), "r"(a[1]), "r"(a[2]), "r"(a[3]), "r"(b[0]), "r"(b[1]));
}

// =====================================================================
// k_prep: OTb (one-hot bf16, 3 copies), Bh/Bl, Zb (3-way bf16 split),
//         x_ext.  196608 + 196608 + 262144 + 69632 = 724992 = 2832*256
// =====================================================================
__global__ void k_prep(const float* __restrict__ x,
                       const float* __restrict__ centers,
                       const float* __restrict__ widths,
                       const float* __restrict__ conseq,
                       const int*   __restrict__ ridx,
                       float* __restrict__ out_xext)
{
    int i = blockIdx.x * 256 + threadIdx.x;
    if (i < 196608) {
        int r = i / 192, q = i % 192;
        int j = q & 63;
        int d = j >> 2, m = j & 3;
        g_OTb[i] = __float2bfloat16((ridx[d * NRULES + r] == m) ? 1.0f : 0.0f);
    } else if (i < 2 * 196608) {
        int e = i - 196608;
        int n = e >> 10, k = e & 1023;
        float v = (n < NCOLS) ? conseq[k * NCOLS + n] : 0.0f;
        __nv_bfloat16 h = __float2bfloat16_rn(v);
        g_Bh[e] = h;
        g_Bl[e] = __float2bfloat16_rn(v - __bfloat162float(h));
    } else if (i < 2 * 196608 + 262144) {
        int e = i - 2 * 196608;
        int b = e >> 6, j = e & 63;
        int d = j >> 2;
        float xv = x[b * DIM + d];
        float c  = centers[j];
        float w  = widths[j];
        float df = xv - c;
        float z  = -(df * df) / (2.0f * w * w) + 1e-9f;
        __nv_bfloat16 h = __float2bfloat16_rn(z);
        float r1 = z - __bfloat162float(h);
        __nv_bfloat16 l = __float2bfloat16_rn(r1);
        float r2 = r1 - __bfloat162float(l);
        g_Zb[b * 192 + j]       = h;
        g_Zb[b * 192 + 64 + j]  = l;
        g_Zb[b * 192 + 128 + j] = __float2bfloat16_rn(r2);
    } else {
        int e = i - (2 * 196608 + 262144);
        if (e < BATCH * IEXT) {
            int b = e / IEXT, ii = e % IEXT;
            out_xext[e] = (ii < DIM) ? x[b * DIM + ii] : 1.0f;
        }
    }
}

// =====================================================================
// k_fire: HMMA GEMM  logits = Zb[4096x192] @ OTb^T[192x1024], exp fused.
// CTA 128 rows x 64 rules, 256 thr (4M x 2N warps, warp 32x32).
// grid (32 M, 16 rule-chunks). 3 CTAs/SM.
// =====================================================================
#define F_STAGE 24576   // A 16KB + B 8KB
#define F_SMB   16384

__device__ __forceinline__ void load_fchunk(uint32_t sbase, int stage,
                                            int mt, int rt0, int ck, int t)
{
    const __nv_bfloat16* Asrc = g_Zb  + (size_t)(mt * 128) * 192 + ck * 64;
    const __nv_bfloat16* Bsrc = g_OTb + (size_t)rt0 * 192 + ck * 64;
    uint32_t sA = sbase + stage * F_STAGE;
    uint32_t sB = sA + F_SMB;
#pragma unroll
    for (int i = 0; i < 4; i++) {          // A: 128 rows x 128B
        int f = t + i * 256, row = f >> 3, c = f & 7;
        CP_ASYNC16(sA + SWZ128(row * 128 + c * 16), Asrc + row * 192 + c * 8);
    }
#pragma unroll
    for (int i = 0; i < 2; i++) {          // B: 64 rows x 128B
        int f = t + i * 256, row = f >> 3, c = f & 7;
        CP_ASYNC16(sB + SWZ128(row * 128 + c * 16), Bsrc + row * 192 + c * 8);
    }
}

__global__ __launch_bounds__(256, 3) void k_fire(float* __restrict__ out_norm)
{
    uint32_t sbase = smem_u32(dyn_smem);
    const int t = threadIdx.x;
    const int lane = t & 31;
    const int wid = t >> 5;
    const int warp_m = wid >> 1;
    const int warp_n = wid & 1;
    const int mt  = blockIdx.x;
    const int rt0 = blockIdx.y * 64;

    float acc[2][4][4];
#pragma unroll
    for (int mi = 0; mi < 2; mi++)
#pragma unroll
        for (int ni = 0; ni < 4; ni++)
#pragma unroll
            for (int q = 0; q < 4; q++) acc[mi][ni][q] = 0.f;

    load_fchunk(sbase, 0, mt, rt0, 0, t);
    CP_COMMIT();

    for (int ch = 0; ch < 3; ch++) {
        if (ch + 1 < 3) {
            load_fchunk(sbase, (ch + 1) & 1, mt, rt0, ch + 1, t);
            CP_COMMIT();
            CP_WAIT1();
        } else {
            CP_WAIT0();
        }
        __syncthreads();

        uint32_t sA = sbase + (ch & 1) * F_STAGE;
        uint32_t sB = sA + F_SMB;

#pragma unroll
        for (int kk = 0; kk < 4; kk++) {
            uint32_t a[2][4];
#pragma unroll
            for (int mi = 0; mi < 2; mi++) {
                int r = warp_m * 32 + mi * 16 + (lane & 15);
                uint32_t off = (uint32_t)(r * 128 + kk * 32 + (lane >> 4) * 16);
                LDSM_X4(a[mi][0], a[mi][1], a[mi][2], a[mi][3], sA + SWZ128(off));
            }
            uint32_t b[4][2];
#pragma unroll
            for (int pr = 0; pr < 2; pr++) {
                int nt8 = 2 * pr + (lane >> 4);
                int r = warp_n * 32 + nt8 * 8 + (lane & 7);
                uint32_t off = (uint32_t)(r * 128 + kk * 32 + ((lane >> 3) & 1) * 16);
                LDSM_X4(b[2 * pr][0], b[2 * pr][1], b[2 * pr + 1][0], b[2 * pr + 1][1],
                        sB + SWZ128(off));
            }
#pragma unroll
            for (int mi = 0; mi < 2; mi++)
#pragma unroll
                for (int ni = 0; ni < 4; ni++)
                    mma16816(acc[mi][ni], a[mi], b[ni]);
        }
        __syncthreads();
    }

    // epilogue: exp + store unnormalized firing
    int r0 = mt * 128 + warp_m * 32 + (lane >> 2);
    int c0 = rt0 + warp_n * 32 + (lane & 3) * 2;
#pragma unroll
    for (int mi = 0; mi < 2; mi++)
#pragma unroll
        for (int ni = 0; ni < 4; ni++) {
            int row = r0 + mi * 16, col = c0 + ni * 8;
            *(float2*)(out_norm + (size_t)row * NRULES + col) =
                make_float2(__expf(acc[mi][ni][0]), __expf(acc[mi][ni][1]));
            *(float2*)(out_norm + (size_t)(row + 8) * NRULES + col) =
                make_float2(__expf(acc[mi][ni][2]), __expf(acc[mi][ni][3]));
        }
}

// =====================================================================
// k_norm: warp per batch row: rowsum -> normalize in place -> bf16 hi/lo.
// 512 blocks x 256 thr (8 rows/block).
// =====================================================================
__global__ void k_norm(float* __restrict__ out_norm)
{
    const int lane = threadIdx.x & 31;
    const int w = threadIdx.x >> 5;
    const int b = blockIdx.x * 8 + w;

    float4* p = (float4*)(out_norm + (size_t)b * NRULES);
    float4 v[8];
    float s = 0.f;
#pragma unroll
    for (int i = 0; i < 8; i++) {
        v[i] = p[lane + i * 32];
        s += (v[i].x + v[i].y) + (v[i].z + v[i].w);
    }
#pragma unroll
    for (int off = 16; off > 0; off >>= 1)
        s += __shfl_xor_sync(0xffffffffu, s, off);
    float inv = 1.0f / (s + 1e-9f);

    __nv_bfloat162* Ah2 = (__nv_bfloat162*)(g_Ah + (size_t)b * NRULES);
    __nv_bfloat162* Al2 = (__nv_bfloat162*)(g_Al + (size_t)b * NRULES);
#pragma unroll
    for (int i = 0; i < 8; i++) {
        float4 u = v[i];
        u.x *= inv; u.y *= inv; u.z *= inv; u.w *= inv;
        p[lane + i * 32] = u;
        __nv_bfloat16 hx = __float2bfloat16_rn(u.x), hy = __float2bfloat16_rn(u.y);
        __nv_bfloat16 hz = __float2bfloat16_rn(u.z), hw = __float2bfloat16_rn(u.w);
        int q = (lane + i * 32) * 2;
        Ah2[q]     = __nv_bfloat162(hx, hy);
        Ah2[q + 1] = __nv_bfloat162(hz, hw);
        Al2[q]     = __nv_bfloat162(__float2bfloat16_rn(u.x - __bfloat162float(hx)),
                                    __float2bfloat16_rn(u.y - __bfloat162float(hy)));
        Al2[q + 1] = __nv_bfloat162(__float2bfloat16_rn(u.z - __bfloat162float(hz)),
                                    __float2bfloat16_rn(u.w - __bfloat162float(hw)));
    }
}

// =====================================================================
// k_tgemm: HMMA bf16 GEMM, hi/lo compensated (3 passes, K_eff=3072).
// CTA 128x64, 256 thr (4M x 2N warps, warp 32x32), 3 CTAs/SM.
// grid (32 M, 3 Ntile x 4 Ksplit) = 384 CTAs.
// =====================================================================
#define STAGE_BYTES 24576   // A 16KB + B 8KB
#define SMB_OFF     16384
#define SM_TOT_G    (2 * STAGE_BYTES)

__device__ __forceinline__ void load_chunk(uint32_t sbase, int stage, int mt, int nt,
                                           int kg, int t)
{
    int pass = kg >> 10, ko = kg & 1023;
    const __nv_bfloat16* Asrc = (pass == 2 ? g_Al : g_Ah) + (size_t)(mt * 128) * NRULES + ko;
    const __nv_bfloat16* Bsrc = (pass == 1 ? g_Bl : g_Bh) + (size_t)(nt * 64) * NRULES + ko;
    uint32_t sA = sbase + stage * STAGE_BYTES;
    uint32_t sB = sA + SMB_OFF;
#pragma unroll
    for (int i = 0; i < 4; i++) {          // A: 128 rows x 128B
        int f = t + i * 256, row = f >> 3, c = f & 7;
        CP_ASYNC16(sA + SWZ128(row * 128 + c * 16), Asrc + row * NRULES + c * 8);
    }
#pragma unroll
    for (int i = 0; i < 2; i++) {          // B: 64 rows x 128B
        int f = t + i * 256, row = f >> 3, c = f & 7;
        CP_ASYNC16(sB + SWZ128(row * 128 + c * 16), Bsrc + row * NRULES + c * 8);
    }
}

__global__ __launch_bounds__(256, 3) void k_tgemm()
{
    uint32_t sbase = smem_u32(dyn_smem);
    const int t = threadIdx.x;
    const int lane = t & 31;
    const int wid = t >> 5;
    const int warp_m = wid >> 1;
    const int warp_n = wid & 1;
    const int mt = blockIdx.x;
    const int nt = blockIdx.y % 3;
    const int ks = blockIdx.y / 3;

    float acc[2][4][4];
#pragma unroll
    for (int mi = 0; mi < 2; mi++)
#pragma unroll
        for (int ni = 0; ni < 4; ni++)
#pragma unroll
            for (int q = 0; q < 4; q++) acc[mi][ni][q] = 0.f;

    load_chunk(sbase, 0, mt, nt, ks * KLOC, t);
    CP_COMMIT();

    for (int ch = 0; ch < NCH; ch++) {
        if (ch + 1 < NCH) {
            load_chunk(sbase, (ch + 1) & 1, mt, nt, ks * KLOC + (ch + 1) * 64, t);
            CP_COMMIT();
            CP_WAIT1();
        } else {
            CP_WAIT0();
        }
        __syncthreads();

        uint32_t sA = sbase + (ch & 1) * STAGE_BYTES;
        uint32_t sB = sA + SMB_OFF;

#pragma unroll
        for (int kk = 0; kk < 4; kk++) {
            uint32_t a[2][4];
#pragma unroll
            for (int mi = 0; mi < 2; mi++) {
                int r = warp_m * 32 + mi * 16 + (lane & 15);
                uint32_t off = (uint32_t)(r * 128 + kk * 32 + (lane >> 4) * 16);
                LDSM_X4(a[mi][0], a[mi][1], a[mi][2], a[mi][3], sA + SWZ128(off));
            }
            uint32_t b[4][2];
#pragma unroll
            for (int pr = 0; pr < 2; pr++) {
                int nt8 = 2 * pr + (lane >> 4);
                int r = warp_n * 32 + nt8 * 8 + (lane & 7);
                uint32_t off = (uint32_t)(r * 128 + kk * 32 + ((lane >> 3) & 1) * 16);
                LDSM_X4(b[2 * pr][0], b[2 * pr][1], b[2 * pr + 1][0], b[2 * pr + 1][1],
                        sB + SWZ128(off));
            }
#pragma unroll
            for (int mi = 0; mi < 2; mi++)
#pragma unroll
                for (int ni = 0; ni < 4; ni++)
                    mma16816(acc[mi][ni], a[mi], b[ni]);
        }
        __syncthreads();
    }

    // epilogue: write fp32 partials
    float* Tp = g_Tp + (size_t)ks * (BATCH * NPAD);
    int r0 = mt * 128 + warp_m * 32 + (lane >> 2);
    int c0 = nt * 64 + warp_n * 32 + (lane & 3) * 2;
#pragma unroll
    for (int mi = 0; mi < 2; mi++)
#pragma unroll
        for (int ni = 0; ni < 4; ni++) {
            int row = r0 + mi * 16, col = c0 + ni * 8;
            *(float2*)(Tp + (size_t)row * NPAD + col) =
                make_float2(acc[mi][ni][0], acc[mi][ni][1]);
            *(float2*)(Tp + (size_t)(row + 8) * NPAD + col) =
                make_float2(acc[mi][ni][2], acc[mi][ni][3]);
        }
}

// =====================================================================
// k_yhat: y[b,c] = sum_i xext[b,i] * sum_s Tp[s][b, i*10+c]
// =====================================================================
__global__ void k_yhat(const float* __restrict__ xext, float* __restrict__ out_y)
{
    int i = blockIdx.x * 256 + threadIdx.x;
    if (i >= BATCH * NCLS) return;
    int b = i / NCLS, c = i % NCLS;
    const float* tb = g_Tp + (size_t)b * NPAD;
    const float* xe = xext + b * IEXT;
    float y = 0.f;
#pragma unroll
    for (int ii = 0; ii < IEXT; ii++) {
        float tsum = 0.f;
#pragma unroll
        for (int s = 0; s < KSPLIT; s++)
            tsum += tb[(size_t)s * (BATCH * NPAD) + ii * NCLS + c];
        y += xe[ii] * tsum;
    }
    out_y[i] = y;
}

// =====================================================================
extern "C" void kernel_launch(void* const* d_in, const int* in_sizes, int n_in,
                              void* d_out, int out_size)
{
    const float* x       = (const float*)d_in[0];
    const float* centers = (const float*)d_in[1];
    const float* widths  = (const float*)d_in[2];
    const float* conseq  = (const float*)d_in[3];
    const int*   ridx    = (const int*)  d_in[4];

    float* out      = (float*)d_out;
    float* out_y    = out;
    float* out_norm = out + BATCH * NCLS;
    float* out_xext = out + BATCH * NCLS + BATCH * NRULES;

    cudaFuncSetAttribute(k_fire,  cudaFuncAttributeMaxDynamicSharedMemorySize, 2 * F_STAGE);
    cudaFuncSetAttribute(k_tgemm, cudaFuncAttributeMaxDynamicSharedMemorySize, SM_TOT_G);

    k_prep<<<2832, 256>>>(x, centers, widths, conseq, ridx, out_xext);
    k_fire<<<dim3(32, 16), 256, 2 * F_STAGE>>>(out_norm);
    k_norm<<<512, 256>>>(out_norm);
    k_tgemm<<<dim3(32, 12), 256, SM_TOT_G>>>();
    k_yhat<<<160, 256>>>(out_xext, out_y);
}

// round 7
// speedup vs baseline: 1.1540x; 1.1540x over previous
#include <cuda_runtime.h>
#include <cuda_fp16.h>
#include <cstdint>

#define BATCH   4096
#define DIM     16
#define NRULES  1024
#define NCLS    10
#define IEXT    17
#define NCOLS   170
#define NPAD    192
#define KSPLIT  4
#define KTOT    2048                 // 2 passes x 1024 (ah*bh, ah*bl)
#define KLOC    (KTOT / KSPLIT)      // 512
#define NCH     (KLOC / 64)          // 8

// single TU-wide dynamic smem symbol
extern __shared__ char dyn_smem[];

// ---------------- static device scratch ----------------
__device__ __half g_Zh[BATCH * 128];      // [b][zh(64)|zl(64)]
__device__ __half g_OTf[NRULES * 128];    // one-hot fp16, [r][j] x2 copies
__device__ __half g_Af[BATCH * NRULES];   // norm_fs fp16 (hi only)
__device__ __half g_Bc[NPAD * 2048];      // [n][ Bh(1024) | Bl(1024) ]
__device__ float  g_Tp[KSPLIT * BATCH * NPAD];   // 12.6 MB partials

// ---------------- helpers ----------------
__device__ __forceinline__ uint32_t smem_u32(const void* p) {
    uint32_t a;
    asm("{ .reg .u64 t; cvta.to.shared.u64 t, %1; cvt.u32.u64 %0, t; }" : "=r"(a) : "l"(p));
    return a;
}
#define SWZ128(o) ((o) ^ (((o) >> 3) & 0x70))

#define CP_ASYNC16(dst, src) \
    asm volatile("cp.async.cg.shared.global [%0], [%1], 16;" :: "r"(dst), "l"(src))
#define CP_COMMIT() asm volatile("cp.async.commit_group;" ::: "memory")
#define CP_WAIT1()  asm volatile("cp.async.wait_group 1;" ::: "memory")
#define CP_WAIT0()  asm volatile("cp.async.wait_group 0;" ::: "memory")

#define LDSM_X4(r0, r1, r2, r3, addr)                                        \
    asm volatile("ldmatrix.sync.aligned.m8n8.x4.shared.b16 {%0,%1,%2,%3}, [%4];" \
        : "=r"(r0), "=r"(r1), "=r"(r2), "=r"(r3) : "r"(addr))

__device__ __forceinline__ void mma16816(float* c, const uint32_t* a, const uint32_t* b) {
    asm volatile(
        "mma.sync.aligned.m16n8k16.row.col.f32.f16.f16.f32 "
        "{%0,%1,%2,%3}, {%4,%5,%6,%7}, {%8,%9}, {%0,%1,%2,%3};"
        : "+f"(c[0]), "+f"(c[1]), "+f"(c[2]), "+f"(c[3])
        : "r"(a[0]), "r"(a[1]), "r"(a[2]), "r"(a[3]), "r"(b[0]), "r"(b[1]));
}

// =====================================================================
// k_prep: OTf (one-hot fp16, 2 copies), Bc (fp16 hi|lo of consequents),
//         Zh (fp16 hi|lo logits), x_ext.
// 131072 + 393216 + 524288 + 69632 = 1118208 = 4368*256
// =====================================================================
__global__ void k_prep(const float* __restrict__ x,
                       const float* __restrict__ centers,
                       const float* __restrict__ widths,
                       const float* __restrict__ conseq,
                       const int*   __restrict__ ridx,
                       float* __restrict__ out_xext)
{
    int i = blockIdx.x * 256 + threadIdx.x;
    if (i < 131072) {
        int r = i >> 7, q = i & 127;
        int j = q & 63;
        int d = j >> 2, m = j & 3;
        g_OTf[i] = __float2half((ridx[d * NRULES + r] == m) ? 1.0f : 0.0f);
    } else if (i < 131072 + 393216) {
        int e = i - 131072;
        int n = e >> 11, k2 = e & 2047;
        int rule = k2 & 1023, lo = k2 >> 10;
        float v = (n < NCOLS) ? conseq[rule * NCOLS + n] : 0.0f;
        __half h = __float2half_rn(v);
        g_Bc[e] = lo ? __float2half_rn(v - __half2float(h)) : h;
    } else if (i < 131072 + 393216 + 524288) {
        int e = i - (131072 + 393216);
        int b = e >> 7, j2 = e & 127;
        int j = j2 & 63, lo = j2 >> 6;
        int d = j >> 2;
        float xv = x[b * DIM + d];
        float c  = centers[j];
        float w  = widths[j];
        float df = xv - c;
        float z  = -(df * df) / (2.0f * w * w) + 1e-9f;
        __half h = __float2half_rn(z);
        g_Zh[e] = lo ? __float2half_rn(z - __half2float(h)) : h;
    } else {
        int e = i - (131072 + 393216 + 524288);
        if (e < BATCH * IEXT) {
            int b = e / IEXT, ii = e % IEXT;
            out_xext[e] = (ii < DIM) ? x[b * DIM + ii] : 1.0f;
        }
    }
}

// =====================================================================
// k_fire: HMMA GEMM  logits = Zh[4096x128] @ OTf^T[128x1024], exp fused.
// CTA 128 rows x 64 rules, 256 thr (4M x 2N warps, warp 32x32).
// grid (32 M, 16 rule-chunks). K=128 -> 2 chunks of 64.
// =====================================================================
#define F_STAGE 24576   // A 16KB + B 8KB
#define F_SMB   16384

__device__ __forceinline__ void load_fchunk(uint32_t sbase, int stage,
                                            int mt, int rt0, int ck, int t)
{
    const __half* Asrc = g_Zh  + (size_t)(mt * 128) * 128 + ck * 64;
    const __half* Bsrc = g_OTf + (size_t)rt0 * 128 + ck * 64;
    uint32_t sA = sbase + stage * F_STAGE;
    uint32_t sB = sA + F_SMB;
#pragma unroll
    for (int i = 0; i < 4; i++) {          // A: 128 rows x 128B
        int f = t + i * 256, row = f >> 3, c = f & 7;
        CP_ASYNC16(sA + SWZ128(row * 128 + c * 16), Asrc + row * 128 + c * 8);
    }
#pragma unroll
    for (int i = 0; i < 2; i++) {          // B: 64 rows x 128B
        int f = t + i * 256, row = f >> 3, c = f & 7;
        CP_ASYNC16(sB + SWZ128(row * 128 + c * 16), Bsrc + row * 128 + c * 8);
    }
}

__global__ __launch_bounds__(256, 3) void k_fire(float* __restrict__ out_norm)
{
    uint32_t sbase = smem_u32(dyn_smem);
    const int t = threadIdx.x;
    const int lane = t & 31;
    const int wid = t >> 5;
    const int warp_m = wid >> 1;
    const int warp_n = wid & 1;
    const int mt  = blockIdx.x;
    const int rt0 = blockIdx.y * 64;

    float acc[2][4][4];
#pragma unroll
    for (int mi = 0; mi < 2; mi++)
#pragma unroll
        for (int ni = 0; ni < 4; ni++)
#pragma unroll
            for (int q = 0; q < 4; q++) acc[mi][ni][q] = 0.f;

    load_fchunk(sbase, 0, mt, rt0, 0, t);
    CP_COMMIT();

    for (int ch = 0; ch < 2; ch++) {
        if (ch + 1 < 2) {
            load_fchunk(sbase, (ch + 1) & 1, mt, rt0, ch + 1, t);
            CP_COMMIT();
            CP_WAIT1();
        } else {
            CP_WAIT0();
        }
        __syncthreads();

        uint32_t sA = sbase + (ch & 1) * F_STAGE;
        uint32_t sB = sA + F_SMB;

#pragma unroll
        for (int kk = 0; kk < 4; kk++) {
            uint32_t a[2][4];
#pragma unroll
            for (int mi = 0; mi < 2; mi++) {
                int r = warp_m * 32 + mi * 16 + (lane & 15);
                uint32_t off = (uint32_t)(r * 128 + kk * 32 + (lane >> 4) * 16);
                LDSM_X4(a[mi][0], a[mi][1], a[mi][2], a[mi][3], sA + SWZ128(off));
            }
            uint32_t b[4][2];
#pragma unroll
            for (int pr = 0; pr < 2; pr++) {
                int nt8 = 2 * pr + (lane >> 4);
                int r = warp_n * 32 + nt8 * 8 + (lane & 7);
                uint32_t off = (uint32_t)(r * 128 + kk * 32 + ((lane >> 3) & 1) * 16);
                LDSM_X4(b[2 * pr][0], b[2 * pr][1], b[2 * pr + 1][0], b[2 * pr + 1][1],
                        sB + SWZ128(off));
            }
#pragma unroll
            for (int mi = 0; mi < 2; mi++)
#pragma unroll
                for (int ni = 0; ni < 4; ni++)
                    mma16816(acc[mi][ni], a[mi], b[ni]);
        }
        __syncthreads();
    }

    // epilogue: exp + store unnormalized firing
    int r0 = mt * 128 + warp_m * 32 + (lane >> 2);
    int c0 = rt0 + warp_n * 32 + (lane & 3) * 2;
#pragma unroll
    for (int mi = 0; mi < 2; mi++)
#pragma unroll
        for (int ni = 0; ni < 4; ni++) {
            int row = r0 + mi * 16, col = c0 + ni * 8;
            *(float2*)(out_norm + (size_t)row * NRULES + col) =
                make_float2(__expf(acc[mi][ni][0]), __expf(acc[mi][ni][1]));
            *(float2*)(out_norm + (size_t)(row + 8) * NRULES + col) =
                make_float2(__expf(acc[mi][ni][2]), __expf(acc[mi][ni][3]));
        }
}

// =====================================================================
// k_norm: warp per batch row: rowsum -> normalize in place -> fp16 A.
// 512 blocks x 256 thr (8 rows/block).
// =====================================================================
__global__ void k_norm(float* __restrict__ out_norm)
{
    const int lane = threadIdx.x & 31;
    const int w = threadIdx.x >> 5;
    const int b = blockIdx.x * 8 + w;

    float4* p = (float4*)(out_norm + (size_t)b * NRULES);
    float4 v[8];
    float s = 0.f;
#pragma unroll
    for (int i = 0; i < 8; i++) {
        v[i] = p[lane + i * 32];
        s += (v[i].x + v[i].y) + (v[i].z + v[i].w);
    }
#pragma unroll
    for (int off = 16; off > 0; off >>= 1)
        s += __shfl_xor_sync(0xffffffffu, s, off);
    float inv = 1.0f / (s + 1e-9f);

    __half2* Af2 = (__half2*)(g_Af + (size_t)b * NRULES);
#pragma unroll
    for (int i = 0; i < 8; i++) {
        float4 u = v[i];
        u.x *= inv; u.y *= inv; u.z *= inv; u.w *= inv;
        p[lane + i * 32] = u;
        int q = (lane + i * 32) * 2;
        Af2[q]     = __floats2half2_rn(u.x, u.y);
        Af2[q + 1] = __floats2half2_rn(u.z, u.w);
    }
}

// =====================================================================
// k_tgemm: HMMA fp16 GEMM, 2-pass hi/lo on B (K_eff=2048).
// CTA 128x64, 256 thr (4M x 2N warps, warp 32x32).
// grid (32 M, 3 Ntile x 4 Ksplit) = 384 CTAs.
// =====================================================================
#define STAGE_BYTES 24576   // A 16KB + B 8KB
#define SMB_OFF     16384
#define SM_TOT_G    (2 * STAGE_BYTES)

__device__ __forceinline__ void load_chunk(uint32_t sbase, int stage, int mt, int nt,
                                           int kg, int t)
{
    const __half* Asrc = g_Af + (size_t)(mt * 128) * NRULES + (kg & 1023);
    const __half* Bsrc = g_Bc + (size_t)(nt * 64) * 2048 + kg;
    uint32_t sA = sbase + stage * STAGE_BYTES;
    uint32_t sB = sA + SMB_OFF;
#pragma unroll
    for (int i = 0; i < 4; i++) {          // A: 128 rows x 128B
        int f = t + i * 256, row = f >> 3, c = f & 7;
        CP_ASYNC16(sA + SWZ128(row * 128 + c * 16), Asrc + row * NRULES + c * 8);
    }
#pragma unroll
    for (int i = 0; i < 2; i++) {          // B: 64 rows x 128B
        int f = t + i * 256, row = f >> 3, c = f & 7;
        CP_ASYNC16(sB + SWZ128(row * 128 + c * 16), Bsrc + row * 2048 + c * 8);
    }
}

__global__ __launch_bounds__(256, 3) void k_tgemm()
{
    uint32_t sbase = smem_u32(dyn_smem);
    const int t = threadIdx.x;
    const int lane = t & 31;
    const int wid = t >> 5;
    const int warp_m = wid >> 1;
    const int warp_n = wid & 1;
    const int mt = blockIdx.x;
    const int nt = blockIdx.y % 3;
    const int ks = blockIdx.y / 3;

    float acc[2][4][4];
#pragma unroll
    for (int mi = 0; mi < 2; mi++)
#pragma unroll
        for (int ni = 0; ni < 4; ni++)
#pragma unroll
            for (int q = 0; q < 4; q++) acc[mi][ni][q] = 0.f;

    load_chunk(sbase, 0, mt, nt, ks * KLOC, t);
    CP_COMMIT();

    for (int ch = 0; ch < NCH; ch++) {
        if (ch + 1 < NCH) {
            load_chunk(sbase, (ch + 1) & 1, mt, nt, ks * KLOC + (ch + 1) * 64, t);
            CP_COMMIT();
            CP_WAIT1();
        } else {
            CP_WAIT0();
        }
        __syncthreads();

        uint32_t sA = sbase + (ch & 1) * STAGE_BYTES;
        uint32_t sB = sA + SMB_OFF;

#pragma unroll
        for (int kk = 0; kk < 4; kk++) {
            uint32_t a[2][4];
#pragma unroll
            for (int mi = 0; mi < 2; mi++) {
                int r = warp_m * 32 + mi * 16 + (lane & 15);
                uint32_t off = (uint32_t)(r * 128 + kk * 32 + (lane >> 4) * 16);
                LDSM_X4(a[mi][0], a[mi][1], a[mi][2], a[mi][3], sA + SWZ128(off));
            }
            uint32_t b[4][2];
#pragma unroll
            for (int pr = 0; pr < 2; pr++) {
                int nt8 = 2 * pr + (lane >> 4);
                int r = warp_n * 32 + nt8 * 8 + (lane & 7);
                uint32_t off = (uint32_t)(r * 128 + kk * 32 + ((lane >> 3) & 1) * 16);
                LDSM_X4(b[2 * pr][0], b[2 * pr][1], b[2 * pr + 1][0], b[2 * pr + 1][1],
                        sB + SWZ128(off));
            }
#pragma unroll
            for (int mi = 0; mi < 2; mi++)
#pragma unroll
                for (int ni = 0; ni < 4; ni++)
                    mma16816(acc[mi][ni], a[mi], b[ni]);
        }
        __syncthreads();
    }

    // epilogue: write fp32 partials
    float* Tp = g_Tp + (size_t)ks * (BATCH * NPAD);
    int r0 = mt * 128 + warp_m * 32 + (lane >> 2);
    int c0 = nt * 64 + warp_n * 32 + (lane & 3) * 2;
#pragma unroll
    for (int mi = 0; mi < 2; mi++)
#pragma unroll
        for (int ni = 0; ni < 4; ni++) {
            int row = r0 + mi * 16, col = c0 + ni * 8;
            *(float2*)(Tp + (size_t)row * NPAD + col) =
                make_float2(acc[mi][ni][0], acc[mi][ni][1]);
            *(float2*)(Tp + (size_t)(row + 8) * NPAD + col) =
                make_float2(acc[mi][ni][2], acc[mi][ni][3]);
        }
}

// =====================================================================
// k_yhat: y[b,c] = sum_i xext[b,i] * sum_s Tp[s][b, i*10+c]
// =====================================================================
__global__ void k_yhat(const float* __restrict__ xext, float* __restrict__ out_y)
{
    int i = blockIdx.x * 256 + threadIdx.x;
    if (i >= BATCH * NCLS) return;
    int b = i / NCLS, c = i % NCLS;
    const float* tb = g_Tp + (size_t)b * NPAD;
    const float* xe = xext + b * IEXT;
    float y = 0.f;
#pragma unroll
    for (int ii = 0; ii < IEXT; ii++) {
        float tsum = 0.f;
#pragma unroll
        for (int s = 0; s < KSPLIT; s++)
            tsum += tb[(size_t)s * (BATCH * NPAD) + ii * NCLS + c];
        y += xe[ii] * tsum;
    }
    out_y[i] = y;
}

// =====================================================================
extern "C" void kernel_launch(void* const* d_in, const int* in_sizes, int n_in,
                              void* d_out, int out_size)
{
    const float* x       = (const float*)d_in[0];
    const float* centers = (const float*)d_in[1];
    const float* widths  = (const float*)d_in[2];
    const float* conseq  = (const float*)d_in[3];
    const int*   ridx    = (const int*)  d_in[4];

    float* out      = (float*)d_out;
    float* out_y    = out;
    float* out_norm = out + BATCH * NCLS;
    float* out_xext = out + BATCH * NCLS + BATCH * NRULES;

    cudaFuncSetAttribute(k_fire,  cudaFuncAttributeMaxDynamicSharedMemorySize, 2 * F_STAGE);
    cudaFuncSetAttribute(k_tgemm, cudaFuncAttributeMaxDynamicSharedMemorySize, SM_TOT_G);

    k_prep<<<4368, 256>>>(x, centers, widths, conseq, ridx, out_xext);
    k_fire<<<dim3(32, 16), 256, 2 * F_STAGE>>>(out_norm);
    k_norm<<<512, 256>>>(out_norm);
    k_tgemm<<<dim3(32, 12), 256, SM_TOT_G>>>();
    k_yhat<<<160, 256>>>(out_xext, out_y);
}

// round 8
// speedup vs baseline: 1.1550x; 1.0008x over previous
#include <cuda_runtime.h>
#include <cuda_fp16.h>
#include <cstdint>

#define BATCH   4096
#define DIM     16
#define NRULES  1024
#define NCLS    10
#define IEXT    17
#define NCOLS   170
#define NPAD    192
#define KSPLIT  4
#define KTOT    2048                 // 2 passes x 1024 (ah*bh, ah*bl)
#define KLOC    (KTOT / KSPLIT)      // 512
#define NCH     (KLOC / 64)          // 8

// single TU-wide dynamic smem symbol
extern __shared__ char dyn_smem[];

// ---------------- static device scratch ----------------
__device__ __half g_Zh[BATCH * 128];      // [b][zh(64)|zl(64)]
__device__ __half g_OTf[NRULES * 128];    // one-hot fp16, [r][j] x2 copies
__device__ __half g_Af[BATCH * NRULES];   // norm_fs fp16 (hi only)
__device__ __half g_Bc[NPAD * 2048];      // [n][ Bh(1024) | Bl(1024) ]
__device__ float  g_Tp[KSPLIT * BATCH * NPAD];   // 12.6 MB partials

// ---------------- helpers ----------------
__device__ __forceinline__ uint32_t smem_u32(const void* p) {
    uint32_t a;
    asm("{ .reg .u64 t; cvta.to.shared.u64 t, %1; cvt.u32.u64 %0, t; }" : "=r"(a) : "l"(p));
    return a;
}
#define SWZ128(o) ((o) ^ (((o) >> 3) & 0x70))

#define CP_ASYNC16(dst, src) \
    asm volatile("cp.async.cg.shared.global [%0], [%1], 16;" :: "r"(dst), "l"(src))
#define CP_COMMIT() asm volatile("cp.async.commit_group;" ::: "memory")
#define CP_WAIT1()  asm volatile("cp.async.wait_group 1;" ::: "memory")
#define CP_WAIT0()  asm volatile("cp.async.wait_group 0;" ::: "memory")

#define LDSM_X4(r0, r1, r2, r3, addr)                                        \
    asm volatile("ldmatrix.sync.aligned.m8n8.x4.shared.b16 {%0,%1,%2,%3}, [%4];" \
        : "=r"(r0), "=r"(r1), "=r"(r2), "=r"(r3) : "r"(addr))

__device__ __forceinline__ void mma16816(float* c, const uint32_t* a, const uint32_t* b) {
    asm volatile(
        "mma.sync.aligned.m16n8k16.row.col.f32.f16.f16.f32 "
        "{%0,%1,%2,%3}, {%4,%5,%6,%7}, {%8,%9}, {%0,%1,%2,%3};"
        : "+f"(c[0]), "+f"(c[1]), "+f"(c[2]), "+f"(c[3])
        : "r"(a[0]), "r"(a[1]), "r"(a[2]), "r"(a[3]), "r"(b[0]), "r"(b[1]));
}

// =====================================================================
// k_prep: OTf (one-hot fp16, 2 copies), Bc (fp16 hi|lo of consequents),
//         Zh (fp16 hi|lo logits), x_ext.
// 131072 + 393216 + 524288 + 69632 = 1118208 = 4368*256
// =====================================================================
__global__ void k_prep(const float* __restrict__ x,
                       const float* __restrict__ centers,
                       const float* __restrict__ widths,
                       const float* __restrict__ conseq,
                       const int*   __restrict__ ridx,
                       float* __restrict__ out_xext)
{
    int i = blockIdx.x * 256 + threadIdx.x;
    if (i < 131072) {
        int r = i >> 7, q = i & 127;
        int j = q & 63;
        int d = j >> 2, m = j & 3;
        g_OTf[i] = __float2half((ridx[d * NRULES + r] == m) ? 1.0f : 0.0f);
    } else if (i < 131072 + 393216) {
        int e = i - 131072;
        int n = e >> 11, k2 = e & 2047;
        int rule = k2 & 1023, lo = k2 >> 10;
        float v = (n < NCOLS) ? conseq[rule * NCOLS + n] : 0.0f;
        __half h = __float2half_rn(v);
        g_Bc[e] = lo ? __float2half_rn(v - __half2float(h)) : h;
    } else if (i < 131072 + 393216 + 524288) {
        int e = i - (131072 + 393216);
        int b = e >> 7, j2 = e & 127;
        int j = j2 & 63, lo = j2 >> 6;
        int d = j >> 2;
        float xv = x[b * DIM + d];
        float c  = centers[j];
        float w  = widths[j];
        float df = xv - c;
        float z  = -(df * df) / (2.0f * w * w) + 1e-9f;
        __half h = __float2half_rn(z);
        g_Zh[e] = lo ? __float2half_rn(z - __half2float(h)) : h;
    } else {
        int e = i - (131072 + 393216 + 524288);
        if (e < BATCH * IEXT) {
            int b = e / IEXT, ii = e % IEXT;
            out_xext[e] = (ii < DIM) ? x[b * DIM + ii] : 1.0f;
        }
    }
}

// =====================================================================
// k_fire: HMMA GEMM  logits = Zh[4096x128] @ OTf^T[128x1024], exp fused.
// CTA 128 rows x 64 rules, 256 thr (4M x 2N warps, warp 32x32).
// grid (32 M, 16 rule-chunks). K=128 -> 2 chunks of 64.
// =====================================================================
#define F_STAGE 24576   // A 16KB + B 8KB
#define F_SMB   16384

__device__ __forceinline__ void load_fchunk(uint32_t sbase, int stage,
                                            int mt, int rt0, int ck, int t)
{
    const __half* Asrc = g_Zh  + (size_t)(mt * 128) * 128 + ck * 64;
    const __half* Bsrc = g_OTf + (size_t)rt0 * 128 + ck * 64;
    uint32_t sA = sbase + stage * F_STAGE;
    uint32_t sB = sA + F_SMB;
#pragma unroll
    for (int i = 0; i < 4; i++) {          // A: 128 rows x 128B
        int f = t + i * 256, row = f >> 3, c = f & 7;
        CP_ASYNC16(sA + SWZ128(row * 128 + c * 16), Asrc + row * 128 + c * 8);
    }
#pragma unroll
    for (int i = 0; i < 2; i++) {          // B: 64 rows x 128B
        int f = t + i * 256, row = f >> 3, c = f & 7;
        CP_ASYNC16(sB + SWZ128(row * 128 + c * 16), Bsrc + row * 128 + c * 8);
    }
}

__global__ __launch_bounds__(256, 3) void k_fire(float* __restrict__ out_norm)
{
    uint32_t sbase = smem_u32(dyn_smem);
    const int t = threadIdx.x;
    const int lane = t & 31;
    const int wid = t >> 5;
    const int warp_m = wid >> 1;
    const int warp_n = wid & 1;
    const int mt  = blockIdx.x;
    const int rt0 = blockIdx.y * 64;

    float acc[2][4][4];
#pragma unroll
    for (int mi = 0; mi < 2; mi++)
#pragma unroll
        for (int ni = 0; ni < 4; ni++)
#pragma unroll
            for (int q = 0; q < 4; q++) acc[mi][ni][q] = 0.f;

    load_fchunk(sbase, 0, mt, rt0, 0, t);
    CP_COMMIT();

    for (int ch = 0; ch < 2; ch++) {
        if (ch + 1 < 2) {
            load_fchunk(sbase, (ch + 1) & 1, mt, rt0, ch + 1, t);
            CP_COMMIT();
            CP_WAIT1();
        } else {
            CP_WAIT0();
        }
        __syncthreads();

        uint32_t sA = sbase + (ch & 1) * F_STAGE;
        uint32_t sB = sA + F_SMB;

#pragma unroll
        for (int kk = 0; kk < 4; kk++) {
            uint32_t a[2][4];
#pragma unroll
            for (int mi = 0; mi < 2; mi++) {
                int r = warp_m * 32 + mi * 16 + (lane & 15);
                uint32_t off = (uint32_t)(r * 128 + kk * 32 + (lane >> 4) * 16);
                LDSM_X4(a[mi][0], a[mi][1], a[mi][2], a[mi][3], sA + SWZ128(off));
            }
            uint32_t b[4][2];
#pragma unroll
            for (int pr = 0; pr < 2; pr++) {
                int nt8 = 2 * pr + (lane >> 4);
                int r = warp_n * 32 + nt8 * 8 + (lane & 7);
                uint32_t off = (uint32_t)(r * 128 + kk * 32 + ((lane >> 3) & 1) * 16);
                LDSM_X4(b[2 * pr][0], b[2 * pr][1], b[2 * pr + 1][0], b[2 * pr + 1][1],
                        sB + SWZ128(off));
            }
#pragma unroll
            for (int mi = 0; mi < 2; mi++)
#pragma unroll
                for (int ni = 0; ni < 4; ni++)
                    mma16816(acc[mi][ni], a[mi], b[ni]);
        }
        __syncthreads();
    }

    // epilogue: exp + store unnormalized firing
    int r0 = mt * 128 + warp_m * 32 + (lane >> 2);
    int c0 = rt0 + warp_n * 32 + (lane & 3) * 2;
#pragma unroll
    for (int mi = 0; mi < 2; mi++)
#pragma unroll
        for (int ni = 0; ni < 4; ni++) {
            int row = r0 + mi * 16, col = c0 + ni * 8;
            *(float2*)(out_norm + (size_t)row * NRULES + col) =
                make_float2(__expf(acc[mi][ni][0]), __expf(acc[mi][ni][1]));
            *(float2*)(out_norm + (size_t)(row + 8) * NRULES + col) =
                make_float2(__expf(acc[mi][ni][2]), __expf(acc[mi][ni][3]));
        }
}

// =====================================================================
// k_norm: warp per batch row: rowsum -> normalize in place -> fp16 A.
// 512 blocks x 256 thr (8 rows/block).
// =====================================================================
__global__ void k_norm(float* __restrict__ out_norm)
{
    const int lane = threadIdx.x & 31;
    const int w = threadIdx.x >> 5;
    const int b = blockIdx.x * 8 + w;

    float4* p = (float4*)(out_norm + (size_t)b * NRULES);
    float4 v[8];
    float s = 0.f;
#pragma unroll
    for (int i = 0; i < 8; i++) {
        v[i] = p[lane + i * 32];
        s += (v[i].x + v[i].y) + (v[i].z + v[i].w);
    }
#pragma unroll
    for (int off = 16; off > 0; off >>= 1)
        s += __shfl_xor_sync(0xffffffffu, s, off);
    float inv = 1.0f / (s + 1e-9f);

    __half2* Af2 = (__half2*)(g_Af + (size_t)b * NRULES);
#pragma unroll
    for (int i = 0; i < 8; i++) {
        float4 u = v[i];
        u.x *= inv; u.y *= inv; u.z *= inv; u.w *= inv;
        p[lane + i * 32] = u;
        int q = (lane + i * 32) * 2;
        Af2[q]     = __floats2half2_rn(u.x, u.y);
        Af2[q + 1] = __floats2half2_rn(u.z, u.w);
    }
}

// =====================================================================
// k_tgemm: HMMA fp16 GEMM, 2-pass hi/lo on B (K_eff=2048).
// CTA 128x96, 128 thr = 4 warps (2M x 2N), warp tile 64x48 (24 frags).
// grid (32 M, 2 Ntile x 4 Ksplit) = 256 CTAs, 2 CTAs/SM.
// =====================================================================
#define STAGE_BYTES 28672   // A 16KB + B 12KB
#define SMB_OFF     16384
#define SM_TOT_G    (2 * STAGE_BYTES)

__device__ __forceinline__ void load_chunk(uint32_t sbase, int stage, int mt, int nt,
                                           int kg, int t)
{
    const __half* Asrc = g_Af + (size_t)(mt * 128) * NRULES + (kg & 1023);
    const __half* Bsrc = g_Bc + (size_t)(nt * 96) * 2048 + kg;
    uint32_t sA = sbase + stage * STAGE_BYTES;
    uint32_t sB = sA + SMB_OFF;
#pragma unroll
    for (int i = 0; i < 8; i++) {          // A: 128 rows x 128B (1024 uint4)
        int f = t + i * 128, row = f >> 3, c = f & 7;
        CP_ASYNC16(sA + SWZ128(row * 128 + c * 16), Asrc + row * NRULES + c * 8);
    }
#pragma unroll
    for (int i = 0; i < 6; i++) {          // B: 96 rows x 128B (768 uint4)
        int f = t + i * 128, row = f >> 3, c = f & 7;
        CP_ASYNC16(sB + SWZ128(row * 128 + c * 16), Bsrc + row * 2048 + c * 8);
    }
}

__global__ __launch_bounds__(128, 2) void k_tgemm()
{
    uint32_t sbase = smem_u32(dyn_smem);
    const int t = threadIdx.x;
    const int lane = t & 31;
    const int wid = t >> 5;
    const int warp_m = wid >> 1;          // 0..1 -> rows warp_m*64
    const int warp_n = wid & 1;           // 0..1 -> cols warp_n*48
    const int mt = blockIdx.x;
    const int nt = blockIdx.y & 1;
    const int ks = blockIdx.y >> 1;

    float acc[4][6][4];
#pragma unroll
    for (int mi = 0; mi < 4; mi++)
#pragma unroll
        for (int ni = 0; ni < 6; ni++)
#pragma unroll
            for (int q = 0; q < 4; q++) acc[mi][ni][q] = 0.f;

    load_chunk(sbase, 0, mt, nt, ks * KLOC, t);
    CP_COMMIT();

    for (int ch = 0; ch < NCH; ch++) {
        if (ch + 1 < NCH) {
            load_chunk(sbase, (ch + 1) & 1, mt, nt, ks * KLOC + (ch + 1) * 64, t);
            CP_COMMIT();
            CP_WAIT1();
        } else {
            CP_WAIT0();
        }
        __syncthreads();

        uint32_t sA = sbase + (ch & 1) * STAGE_BYTES;
        uint32_t sB = sA + SMB_OFF;

#pragma unroll
        for (int kk = 0; kk < 4; kk++) {
            uint32_t a[4][4];
#pragma unroll
            for (int mi = 0; mi < 4; mi++) {
                int r = warp_m * 64 + mi * 16 + (lane & 15);
                uint32_t off = (uint32_t)(r * 128 + kk * 32 + (lane >> 4) * 16);
                LDSM_X4(a[mi][0], a[mi][1], a[mi][2], a[mi][3], sA + SWZ128(off));
            }
            uint32_t b[6][2];
#pragma unroll
            for (int pr = 0; pr < 3; pr++) {
                int nt8 = 2 * pr + (lane >> 4);
                int r = warp_n * 48 + nt8 * 8 + (lane & 7);
                uint32_t off = (uint32_t)(r * 128 + kk * 32 + ((lane >> 3) & 1) * 16);
                LDSM_X4(b[2 * pr][0], b[2 * pr][1], b[2 * pr + 1][0], b[2 * pr + 1][1],
                        sB + SWZ128(off));
            }
#pragma unroll
            for (int mi = 0; mi < 4; mi++)
#pragma unroll
                for (int ni = 0; ni < 6; ni++)
                    mma16816(acc[mi][ni], a[mi], b[ni]);
        }
        __syncthreads();
    }

    // epilogue: write fp32 partials
    float* Tp = g_Tp + (size_t)ks * (BATCH * NPAD);
    int r0 = mt * 128 + warp_m * 64 + (lane >> 2);
    int c0 = nt * 96 + warp_n * 48 + (lane & 3) * 2;
#pragma unroll
    for (int mi = 0; mi < 4; mi++)
#pragma unroll
        for (int ni = 0; ni < 6; ni++) {
            int row = r0 + mi * 16, col = c0 + ni * 8;
            *(float2*)(Tp + (size_t)row * NPAD + col) =
                make_float2(acc[mi][ni][0], acc[mi][ni][1]);
            *(float2*)(Tp + (size_t)(row + 8) * NPAD + col) =
                make_float2(acc[mi][ni][2], acc[mi][ni][3]);
        }
}

// =====================================================================
// k_yhat: y[b,c] = sum_i xext[b,i] * sum_s Tp[s][b, i*10+c]
// =====================================================================
__global__ void k_yhat(const float* __restrict__ xext, float* __restrict__ out_y)
{
    int i = blockIdx.x * 256 + threadIdx.x;
    if (i >= BATCH * NCLS) return;
    int b = i / NCLS, c = i % NCLS;
    const float* tb = g_Tp + (size_t)b * NPAD;
    const float* xe = xext + b * IEXT;
    float y = 0.f;
#pragma unroll
    for (int ii = 0; ii < IEXT; ii++) {
        float tsum = 0.f;
#pragma unroll
        for (int s = 0; s < KSPLIT; s++)
            tsum += tb[(size_t)s * (BATCH * NPAD) + ii * NCLS + c];
        y += xe[ii] * tsum;
    }
    out_y[i] = y;
}

// =====================================================================
extern "C" void kernel_launch(void* const* d_in, const int* in_sizes, int n_in,
                              void* d_out, int out_size)
{
    const float* x       = (const float*)d_in[0];
    const float* centers = (const float*)d_in[1];
    const float* widths  = (const float*)d_in[2];
    const float* conseq  = (const float*)d_in[3];
    const int*   ridx    = (const int*)  d_in[4];

    float* out      = (float*)d_out;
    float* out_y    = out;
    float* out_norm = out + BATCH * NCLS;
    float* out_xext = out + BATCH * NCLS + BATCH * NRULES;

    cudaFuncSetAttribute(k_fire,  cudaFuncAttributeMaxDynamicSharedMemorySize, 2 * F_STAGE);
    cudaFuncSetAttribute(k_tgemm, cudaFuncAttributeMaxDynamicSharedMemorySize, SM_TOT_G);

    k_prep<<<4368, 256>>>(x, centers, widths, conseq, ridx, out_xext);
    k_fire<<<dim3(32, 16), 256, 2 * F_STAGE>>>(out_norm);
    k_norm<<<512, 256>>>(out_norm);
    k_tgemm<<<dim3(32, 8), 128, SM_TOT_G>>>();
    k_yhat<<<160, 256>>>(out_xext, out_y);
}